// round 3
// baseline (speedup 1.0000x reference)
#include <cuda_runtime.h>
#include <math.h>

#define NN 20000     // num nodes
#define EE 256000    // num edges
#define HD 128       // hidden dim
#define HD2 256      // 2*HD
#define BQ 2048      // query pairs

// ---------------- scratch (device globals; no allocation allowed) ------------
__device__ float g_x[NN * HD];      // embed[h]
__device__ float g_agg1[NN * HD];   // layer1 neighbor agg
__device__ float g_x1[NN * HD];     // layer1 output (post relu)
__device__ float g_agg2[NN * HD2];  // layer2 neighbor agg
__device__ float g_z[NN * HD];      // latent z
__device__ float g_hr[BQ * HD];     // head * rel

// ---------------- zero agg buffers ------------------------------------------
__global__ void zero_kernel() {
    int i = blockIdx.x * blockDim.x + threadIdx.x;
    // zero g_agg1 (NN*HD floats) and g_agg2 (NN*HD2 floats) via float4
    const int n1 = NN * HD / 4;
    const int n2 = NN * HD2 / 4;
    float4 zv = make_float4(0.f, 0.f, 0.f, 0.f);
    if (i < n1) ((float4*)g_agg1)[i] = zv;
    if (i < n2) ((float4*)g_agg2)[i] = zv;
}

// ---------------- gather: x = embed[h] ---------------------------------------
__global__ void gather_kernel(const int* __restrict__ h, const float* __restrict__ embed) {
    int i = blockIdx.x * blockDim.x + threadIdx.x;   // over NN*HD
    if (i < NN * HD) {
        int row = i >> 7;
        int col = i & 127;
        g_x[i] = embed[h[row] * HD + col];
    }
}

// ---------------- edge message, layer 1 (blocks 2x2) --------------------------
// warp per edge. lane owns diagonal blocks 2*lane and 2*lane+1.
__global__ __launch_bounds__(128) void edge1_kernel(
    const int* __restrict__ src, const int* __restrict__ dst,
    const int* __restrict__ et, const float* __restrict__ norm,
    const float* __restrict__ W1)
{
    int e = blockIdx.x * 4 + (threadIdx.x >> 5);
    int lane = threadIdx.x & 31;
    if (e >= EE) return;
    int s = src[e], d = dst[e], r = et[e];
    float nm = norm[e];
    float4 xv = *(const float4*)(g_x + s * HD + lane * 4);
    const float* wp = W1 + r * 256 + lane * 8;   // 2 blocks * 4 floats
    float4 w0 = *(const float4*)(wp);            // block 2*lane: [i0o0,i0o1,i1o0,i1o1]
    float4 w1 = *(const float4*)(wp + 4);        // block 2*lane+1
    float m0 = (xv.x * w0.x + xv.y * w0.z) * nm;
    float m1 = (xv.x * w0.y + xv.y * w0.w) * nm;
    float m2 = (xv.z * w1.x + xv.w * w1.z) * nm;
    float m3 = (xv.z * w1.y + xv.w * w1.w) * nm;
    float* out = g_agg1 + d * HD + lane * 4;
    atomicAdd(out + 0, m0);
    atomicAdd(out + 1, m1);
    atomicAdd(out + 2, m2);
    atomicAdd(out + 3, m3);
}

// ---------------- self loop layer 1: x1 = relu(agg1 + x@lw1 + b1) ------------
__global__ __launch_bounds__(128) void selfloop1_kernel(
    const float* __restrict__ lw1, const float* __restrict__ b1)
{
    int r0 = blockIdx.x * 16;      // 16 rows per block, 20000/16 = 1250 exact
    int k = threadIdx.x;           // output column
    __shared__ float xs[16][HD];
    #pragma unroll
    for (int r = 0; r < 16; r++) xs[r][k] = g_x[(r0 + r) * HD + k];
    __syncthreads();
    float acc[16];
    #pragma unroll
    for (int r = 0; r < 16; r++) acc[r] = 0.f;
    #pragma unroll 4
    for (int j = 0; j < HD; j++) {
        float w = __ldg(lw1 + j * HD + k);
        #pragma unroll
        for (int r = 0; r < 16; r++) acc[r] += xs[r][j] * w;
    }
    float bias = b1[k];
    #pragma unroll
    for (int r = 0; r < 16; r++) {
        float v = acc[r] + bias + g_agg1[(r0 + r) * HD + k];
        g_x1[(r0 + r) * HD + k] = fmaxf(v, 0.f);
    }
}

// ---------------- edge message, layer 2 (blocks 2x4) --------------------------
__global__ __launch_bounds__(128) void edge2_kernel(
    const int* __restrict__ src, const int* __restrict__ dst,
    const int* __restrict__ et, const float* __restrict__ norm,
    const float* __restrict__ W2)
{
    int e = blockIdx.x * 4 + (threadIdx.x >> 5);
    int lane = threadIdx.x & 31;
    if (e >= EE) return;
    int s = src[e], d = dst[e], r = et[e];
    float nm = norm[e];
    float4 xv = *(const float4*)(g_x1 + s * HD + lane * 4);
    const float* wp = W2 + r * 512 + lane * 16;  // 2 blocks * (2x4) floats
    float4 wa0 = *(const float4*)(wp);           // block 2*lane, input row 0
    float4 wa1 = *(const float4*)(wp + 4);       // block 2*lane, input row 1
    float4 wb0 = *(const float4*)(wp + 8);       // block 2*lane+1, input row 0
    float4 wb1 = *(const float4*)(wp + 12);
    float* out = g_agg2 + d * HD2 + lane * 8;
    atomicAdd(out + 0, (xv.x * wa0.x + xv.y * wa1.x) * nm);
    atomicAdd(out + 1, (xv.x * wa0.y + xv.y * wa1.y) * nm);
    atomicAdd(out + 2, (xv.x * wa0.z + xv.y * wa1.z) * nm);
    atomicAdd(out + 3, (xv.x * wa0.w + xv.y * wa1.w) * nm);
    atomicAdd(out + 4, (xv.z * wb0.x + xv.w * wb1.x) * nm);
    atomicAdd(out + 5, (xv.z * wb0.y + xv.w * wb1.y) * nm);
    atomicAdd(out + 6, (xv.z * wb0.z + xv.w * wb1.z) * nm);
    atomicAdd(out + 7, (xv.z * wb0.w + xv.w * wb1.w) * nm);
}

// ------- self loop layer 2 + gaussian: z = m + sqrt(softplus(hv)+1e-8)*eps ----
__global__ __launch_bounds__(256) void selfloop2_kernel(
    const float* __restrict__ lw2, const float* __restrict__ b2,
    const float* __restrict__ eps)
{
    int r0 = blockIdx.x * 8;       // 8 rows per block, 20000/8 = 2500 exact
    int k = threadIdx.x;           // output column 0..255
    __shared__ float xs[8][HD];
    __shared__ float outs[8][HD2];
    for (int i = k; i < 8 * HD; i += 256)
        xs[i >> 7][i & 127] = g_x1[(r0 + (i >> 7)) * HD + (i & 127)];
    __syncthreads();
    float acc[8];
    #pragma unroll
    for (int r = 0; r < 8; r++) acc[r] = 0.f;
    #pragma unroll 4
    for (int j = 0; j < HD; j++) {
        float w = __ldg(lw2 + j * HD2 + k);
        #pragma unroll
        for (int r = 0; r < 8; r++) acc[r] += xs[r][j] * w;
    }
    float bias = b2[k];
    #pragma unroll
    for (int r = 0; r < 8; r++)
        outs[r][k] = acc[r] + bias + g_agg2[(r0 + r) * HD2 + k];
    __syncthreads();
    for (int i = k; i < 8 * HD; i += 256) {
        int r = i >> 7, c = i & 127;
        float mu = outs[r][c];
        float hv = outs[r][c + HD];
        // numerically stable softplus = max(x,0) + log1p(exp(-|x|))
        float sp = fmaxf(hv, 0.f) + log1pf(expf(-fabsf(hv)));
        float var = sp + 1e-8f;
        int row = r0 + r;
        g_z[row * HD + c] = mu + sqrtf(var) * eps[row * HD + c];
    }
}

// ---------------- hr = z[head] * w_rel[rel] ----------------------------------
__global__ __launch_bounds__(128) void hr_kernel(
    const int* __restrict__ head_ids, const int* __restrict__ rel_ids,
    const float* __restrict__ w_rel)
{
    int b = blockIdx.x;
    int k = threadIdx.x;
    g_hr[b * HD + k] = g_z[head_ids[b] * HD + k] * w_rel[rel_ids[b] * HD + k];
}

// ---------------- decoder GEMM: scores = hr @ z^T ----------------------------
// A = g_hr [2048,128] row-major, B = g_z [20000,128] row-major (both K-contig)
// C[m][n] = dot_k A[m][k] * B[n][k].  128x128 tile, 8x8 per thread, K=128 staged.
#define BM 128
#define BN 128
#define LDA (BM + 1)
#define LDB (BN + 1)
__global__ __launch_bounds__(256) void decoder_gemm(float* __restrict__ C) {
    extern __shared__ float smem[];
    float* As = smem;                 // [128][LDA]  (k-major, transposed)
    float* Bs = smem + HD * LDA;      // [128][LDB]
    int m0 = blockIdx.y * BM;
    int n0 = blockIdx.x * BN;
    int t = threadIdx.x;

    // load A tile: 128 rows x 32 float4, always in bounds (2048 % 128 == 0)
    const float4* A4 = (const float4*)(g_hr + m0 * HD);
    #pragma unroll
    for (int j = 0; j < 16; j++) {
        int idx = t + j * 256;
        int m = idx >> 5;
        int k4 = (idx & 31) << 2;
        float4 v = A4[idx];
        As[(k4 + 0) * LDA + m] = v.x;
        As[(k4 + 1) * LDA + m] = v.y;
        As[(k4 + 2) * LDA + m] = v.z;
        As[(k4 + 3) * LDA + m] = v.w;
    }
    // load B tile (guard last tile: 20000 % 128 = 32)
    #pragma unroll
    for (int j = 0; j < 16; j++) {
        int idx = t + j * 256;
        int n = idx >> 5;
        int k4 = (idx & 31) << 2;
        float4 v = make_float4(0.f, 0.f, 0.f, 0.f);
        if (n0 + n < NN) v = *(const float4*)(g_z + (n0 + n) * HD + k4);
        Bs[(k4 + 0) * LDB + n] = v.x;
        Bs[(k4 + 1) * LDB + n] = v.y;
        Bs[(k4 + 2) * LDB + n] = v.z;
        Bs[(k4 + 3) * LDB + n] = v.w;
    }
    __syncthreads();

    int tx = t & 15, ty = t >> 4;
    int mr = ty * 8, nr = tx * 8;
    float acc[8][8];
    #pragma unroll
    for (int i = 0; i < 8; i++)
        #pragma unroll
        for (int j = 0; j < 8; j++) acc[i][j] = 0.f;

    #pragma unroll 8
    for (int k = 0; k < HD; k++) {
        float a[8], b[8];
        #pragma unroll
        for (int i = 0; i < 8; i++) a[i] = As[k * LDA + mr + i];
        #pragma unroll
        for (int j = 0; j < 8; j++) b[j] = Bs[k * LDB + nr + j];
        #pragma unroll
        for (int i = 0; i < 8; i++)
            #pragma unroll
            for (int j = 0; j < 8; j++) acc[i][j] += a[i] * b[j];
    }

    #pragma unroll
    for (int i = 0; i < 8; i++) {
        int m = m0 + mr + i;
        #pragma unroll
        for (int j = 0; j < 8; j++) {
            int n = n0 + nr + j;
            if (n < NN) C[(long)m * NN + n] = acc[i][j];
        }
    }
}

// ---------------- launch ------------------------------------------------------
extern "C" void kernel_launch(void* const* d_in, const int* in_sizes, int n_in,
                              void* d_out, int out_size) {
    const int*   h        = (const int*)d_in[0];
    const int*   src      = (const int*)d_in[1];
    const int*   dst      = (const int*)d_in[2];
    const int*   etypes   = (const int*)d_in[3];
    const float* norm     = (const float*)d_in[4];
    const int*   head_ids = (const int*)d_in[5];
    const int*   rel_ids  = (const int*)d_in[6];
    const float* embed    = (const float*)d_in[7];
    const float* W1       = (const float*)d_in[8];
    const float* lw1      = (const float*)d_in[9];
    const float* b1       = (const float*)d_in[10];
    const float* W2       = (const float*)d_in[11];
    const float* lw2      = (const float*)d_in[12];
    const float* b2       = (const float*)d_in[13];
    const float* w_rel    = (const float*)d_in[14];
    const float* eps      = (const float*)d_in[15];
    float* out = (float*)d_out;

    // zero aggregation buffers: max(NN*HD/4, NN*HD2/4) = 1,280,000 float4
    zero_kernel<<<(NN * HD2 / 4 + 255) / 256, 256>>>();
    gather_kernel<<<(NN * HD + 255) / 256, 256>>>(h, embed);
    edge1_kernel<<<EE / 4, 128>>>(src, dst, etypes, norm, W1);
    selfloop1_kernel<<<NN / 16, 128>>>(lw1, b1);
    edge2_kernel<<<EE / 4, 128>>>(src, dst, etypes, norm, W2);
    selfloop2_kernel<<<NN / 8, 256>>>(lw2, b2, eps);
    hr_kernel<<<BQ, 128>>>(head_ids, rel_ids, w_rel);

    static int smem_set = 0;
    int smem_bytes = (HD * LDA + HD * LDB) * sizeof(float);  // ~132 KB
    if (!smem_set) {
        cudaFuncSetAttribute(decoder_gemm,
                             cudaFuncAttributeMaxDynamicSharedMemorySize, smem_bytes);
        smem_set = 1;
    }
    dim3 grid((NN + BN - 1) / BN, BQ / BM);   // (157, 16)
    decoder_gemm<<<grid, 256, smem_bytes>>>(out);
}

// round 8
// speedup vs baseline: 1.5043x; 1.5043x over previous
#include <cuda_runtime.h>
#include <math.h>

#define NN 20000     // num nodes
#define EE 256000    // num edges
#define HD 128       // hidden dim
#define HD2 256      // 2*HD
#define BQ 2048      // query pairs

// ---------------- scratch (device globals; no allocation allowed) ------------
__device__ float g_x[NN * HD];      // embed[h]
__device__ float g_agg1[NN * HD];   // layer1 neighbor agg
__device__ float g_x1[NN * HD];     // layer1 output (post relu)
__device__ float g_agg2[NN * HD2];  // layer2 neighbor agg
__device__ float g_z[NN * HD];      // latent z
__device__ float g_hr[BQ * HD];     // head * rel

// ---------------- zero agg buffers ------------------------------------------
__global__ void zero_kernel() {
    int i = blockIdx.x * blockDim.x + threadIdx.x;
    const int n1 = NN * HD / 4;
    const int n2 = NN * HD2 / 4;
    float4 zv = make_float4(0.f, 0.f, 0.f, 0.f);
    if (i < n1) ((float4*)g_agg1)[i] = zv;
    if (i < n2) ((float4*)g_agg2)[i] = zv;
}

// ---------------- gather: x = embed[h] ---------------------------------------
__global__ void gather_kernel(const int* __restrict__ h, const float* __restrict__ embed) {
    int i = blockIdx.x * blockDim.x + threadIdx.x;   // over NN*HD
    if (i < NN * HD) {
        int row = i >> 7;
        int col = i & 127;
        g_x[i] = embed[h[row] * HD + col];
    }
}

// ---------------- edge message, layer 1 (blocks 2x2) --------------------------
__global__ __launch_bounds__(128) void edge1_kernel(
    const int* __restrict__ src, const int* __restrict__ dst,
    const int* __restrict__ et, const float* __restrict__ norm,
    const float* __restrict__ W1)
{
    int e = blockIdx.x * 4 + (threadIdx.x >> 5);
    int lane = threadIdx.x & 31;
    if (e >= EE) return;
    int s = src[e], d = dst[e], r = et[e];
    float nm = norm[e];
    float4 xv = *(const float4*)(g_x + s * HD + lane * 4);
    const float* wp = W1 + r * 256 + lane * 8;
    float4 w0 = *(const float4*)(wp);
    float4 w1 = *(const float4*)(wp + 4);
    float m0 = (xv.x * w0.x + xv.y * w0.z) * nm;
    float m1 = (xv.x * w0.y + xv.y * w0.w) * nm;
    float m2 = (xv.z * w1.x + xv.w * w1.z) * nm;
    float m3 = (xv.z * w1.y + xv.w * w1.w) * nm;
    float* out = g_agg1 + d * HD + lane * 4;
    atomicAdd(out + 0, m0);
    atomicAdd(out + 1, m1);
    atomicAdd(out + 2, m2);
    atomicAdd(out + 3, m3);
}

// ---------------- self loop layer 1: x1 = relu(agg1 + x@lw1 + b1) ------------
__global__ __launch_bounds__(128) void selfloop1_kernel(
    const float* __restrict__ lw1, const float* __restrict__ b1)
{
    int r0 = blockIdx.x * 16;
    int k = threadIdx.x;
    __shared__ float xs[16][HD];
    #pragma unroll
    for (int r = 0; r < 16; r++) xs[r][k] = g_x[(r0 + r) * HD + k];
    __syncthreads();
    float acc[16];
    #pragma unroll
    for (int r = 0; r < 16; r++) acc[r] = 0.f;
    #pragma unroll 4
    for (int j = 0; j < HD; j++) {
        float w = __ldg(lw1 + j * HD + k);
        #pragma unroll
        for (int r = 0; r < 16; r++) acc[r] += xs[r][j] * w;
    }
    float bias = b1[k];
    #pragma unroll
    for (int r = 0; r < 16; r++) {
        float v = acc[r] + bias + g_agg1[(r0 + r) * HD + k];
        g_x1[(r0 + r) * HD + k] = fmaxf(v, 0.f);
    }
}

// ---------------- edge message, layer 2 (blocks 2x4) --------------------------
__global__ __launch_bounds__(128) void edge2_kernel(
    const int* __restrict__ src, const int* __restrict__ dst,
    const int* __restrict__ et, const float* __restrict__ norm,
    const float* __restrict__ W2)
{
    int e = blockIdx.x * 4 + (threadIdx.x >> 5);
    int lane = threadIdx.x & 31;
    if (e >= EE) return;
    int s = src[e], d = dst[e], r = et[e];
    float nm = norm[e];
    float4 xv = *(const float4*)(g_x1 + s * HD + lane * 4);
    const float* wp = W2 + r * 512 + lane * 16;
    float4 wa0 = *(const float4*)(wp);
    float4 wa1 = *(const float4*)(wp + 4);
    float4 wb0 = *(const float4*)(wp + 8);
    float4 wb1 = *(const float4*)(wp + 12);
    float* out = g_agg2 + d * HD2 + lane * 8;
    atomicAdd(out + 0, (xv.x * wa0.x + xv.y * wa1.x) * nm);
    atomicAdd(out + 1, (xv.x * wa0.y + xv.y * wa1.y) * nm);
    atomicAdd(out + 2, (xv.x * wa0.z + xv.y * wa1.z) * nm);
    atomicAdd(out + 3, (xv.x * wa0.w + xv.y * wa1.w) * nm);
    atomicAdd(out + 4, (xv.z * wb0.x + xv.w * wb1.x) * nm);
    atomicAdd(out + 5, (xv.z * wb0.y + xv.w * wb1.y) * nm);
    atomicAdd(out + 6, (xv.z * wb0.z + xv.w * wb1.z) * nm);
    atomicAdd(out + 7, (xv.z * wb0.w + xv.w * wb1.w) * nm);
}

// ------- self loop layer 2 + gaussian: z = m + sqrt(softplus(hv)+1e-8)*eps ----
__global__ __launch_bounds__(256) void selfloop2_kernel(
    const float* __restrict__ lw2, const float* __restrict__ b2,
    const float* __restrict__ eps)
{
    int r0 = blockIdx.x * 8;
    int k = threadIdx.x;
    __shared__ float xs[8][HD];
    __shared__ float outs[8][HD2];
    for (int i = k; i < 8 * HD; i += 256)
        xs[i >> 7][i & 127] = g_x1[(r0 + (i >> 7)) * HD + (i & 127)];
    __syncthreads();
    float acc[8];
    #pragma unroll
    for (int r = 0; r < 8; r++) acc[r] = 0.f;
    #pragma unroll 4
    for (int j = 0; j < HD; j++) {
        float w = __ldg(lw2 + j * HD2 + k);
        #pragma unroll
        for (int r = 0; r < 8; r++) acc[r] += xs[r][j] * w;
    }
    float bias = b2[k];
    #pragma unroll
    for (int r = 0; r < 8; r++)
        outs[r][k] = acc[r] + bias + g_agg2[(r0 + r) * HD2 + k];
    __syncthreads();
    for (int i = k; i < 8 * HD; i += 256) {
        int r = i >> 7, c = i & 127;
        float mu = outs[r][c];
        float hv = outs[r][c + HD];
        float sp = fmaxf(hv, 0.f) + log1pf(expf(-fabsf(hv)));
        float var = sp + 1e-8f;
        int row = r0 + r;
        g_z[row * HD + c] = mu + sqrtf(var) * eps[row * HD + c];
    }
}

// ---------------- hr = z[head] * w_rel[rel] ----------------------------------
__global__ __launch_bounds__(128) void hr_kernel(
    const int* __restrict__ head_ids, const int* __restrict__ rel_ids,
    const float* __restrict__ w_rel)
{
    int b = blockIdx.x;
    int k = threadIdx.x;
    g_hr[b * HD + k] = g_z[head_ids[b] * HD + k] * w_rel[rel_ids[b] * HD + k];
}

// ---------------- decoder GEMM via TF32 tensor cores -------------------------
// scores[m][n] = sum_k hr[m][k] * z[n][k].  A=[2048,128], B=[20000,128], both
// K-contiguous.  Tile 128x128, K=128 fully staged.  8 warps, layout 4(M)x2(N),
// warp tile 32x64 via mma.sync.m16n8k8 tf32 (2 M-subtiles x 8 N-subtiles).
#define BM 128
#define BN 128
#define LDT 132      // padded row length for smem tiles (bank-conflict-free)

__device__ __forceinline__ unsigned f2tf32(float f) {
    unsigned u;
    asm("cvt.rna.tf32.f32 %0, %1;" : "=r"(u) : "f"(f));
    return u;
}

__device__ __forceinline__ void mma_tf32(float* d,
    unsigned a0, unsigned a1, unsigned a2, unsigned a3,
    unsigned b0, unsigned b1)
{
    asm volatile(
        "mma.sync.aligned.m16n8k8.row.col.f32.tf32.tf32.f32 "
        "{%0,%1,%2,%3}, {%4,%5,%6,%7}, {%8,%9}, {%0,%1,%2,%3};\n"
        : "+f"(d[0]), "+f"(d[1]), "+f"(d[2]), "+f"(d[3])
        : "r"(a0), "r"(a1), "r"(a2), "r"(a3), "r"(b0), "r"(b1));
}

__global__ __launch_bounds__(256) void decoder_gemm(float* __restrict__ C) {
    extern __shared__ unsigned smem[];
    unsigned* As = smem;              // [BM][LDT]  tf32, [m][k]
    unsigned* Bs = smem + BM * LDT;   // [BN][LDT]  tf32, [n][k]
    int m0 = blockIdx.y * BM;
    int n0 = blockIdx.x * BN;
    int t = threadIdx.x;

    // stage A tile (always in bounds: 2048 % 128 == 0), convert fp32 -> tf32
    const float4* A4 = (const float4*)(g_hr + m0 * HD);
    #pragma unroll
    for (int j = 0; j < 16; j++) {
        int idx = t + j * 256;
        int m = idx >> 5;
        int k4 = (idx & 31) << 2;
        float4 v = A4[idx];
        unsigned* p = As + m * LDT + k4;
        p[0] = f2tf32(v.x); p[1] = f2tf32(v.y);
        p[2] = f2tf32(v.z); p[3] = f2tf32(v.w);
    }
    // stage B tile (guard last tile: 20000 % 128 == 32)
    #pragma unroll
    for (int j = 0; j < 16; j++) {
        int idx = t + j * 256;
        int n = idx >> 5;
        int k4 = (idx & 31) << 2;
        float4 v = make_float4(0.f, 0.f, 0.f, 0.f);
        if (n0 + n < NN) v = *(const float4*)(g_z + (n0 + n) * HD + k4);
        unsigned* p = Bs + n * LDT + k4;
        p[0] = f2tf32(v.x); p[1] = f2tf32(v.y);
        p[2] = f2tf32(v.z); p[3] = f2tf32(v.w);
    }
    __syncthreads();

    int warp = t >> 5;
    int lane = t & 31;
    int warpM = warp >> 1;            // 0..3  -> m offset warpM*32
    int warpN = warp & 1;             // 0..1  -> n offset warpN*64
    int lr = lane >> 2;               // lane/4: row-in-8 group
    int lc = lane & 3;                // lane%4: k-in-4 group

    float acc[2][8][4];
    #pragma unroll
    for (int i = 0; i < 2; i++)
        #pragma unroll
        for (int j = 0; j < 8; j++)
            #pragma unroll
            for (int c = 0; c < 4; c++) acc[i][j][c] = 0.f;

    const unsigned* Abase = As + (warpM * 32 + lr) * LDT + lc;
    const unsigned* Bbase = Bs + (warpN * 64 + lr) * LDT + lc;

    #pragma unroll
    for (int kt = 0; kt < 16; kt++) {
        int k0 = kt * 8;
        unsigned a[2][4];
        #pragma unroll
        for (int i = 0; i < 2; i++) {
            const unsigned* ap = Abase + i * 16 * LDT + k0;
            a[i][0] = ap[0];
            a[i][1] = ap[8 * LDT];
            a[i][2] = ap[4];
            a[i][3] = ap[8 * LDT + 4];
        }
        unsigned b[8][2];
        #pragma unroll
        for (int j = 0; j < 8; j++) {
            const unsigned* bp = Bbase + j * 8 * LDT + k0;
            b[j][0] = bp[0];
            b[j][1] = bp[4];
        }
        #pragma unroll
        for (int i = 0; i < 2; i++)
            #pragma unroll
            for (int j = 0; j < 8; j++)
                mma_tf32(acc[i][j], a[i][0], a[i][1], a[i][2], a[i][3],
                         b[j][0], b[j][1]);
    }

    // store: c0/c1 at (row, 2*lc), (row, 2*lc+1); c2/c3 at row+8
    #pragma unroll
    for (int i = 0; i < 2; i++) {
        int mrow = m0 + warpM * 32 + i * 16 + lr;
        #pragma unroll
        for (int j = 0; j < 8; j++) {
            int n = n0 + warpN * 64 + j * 8 + 2 * lc;
            if (n < NN) {
                float2 v0 = make_float2(acc[i][j][0], acc[i][j][1]);
                float2 v1 = make_float2(acc[i][j][2], acc[i][j][3]);
                *(float2*)(C + (long)mrow * NN + n) = v0;
                *(float2*)(C + (long)(mrow + 8) * NN + n) = v1;
            }
        }
    }
}

// ---------------- launch ------------------------------------------------------
extern "C" void kernel_launch(void* const* d_in, const int* in_sizes, int n_in,
                              void* d_out, int out_size) {
    const int*   h        = (const int*)d_in[0];
    const int*   src      = (const int*)d_in[1];
    const int*   dst      = (const int*)d_in[2];
    const int*   etypes   = (const int*)d_in[3];
    const float* norm     = (const float*)d_in[4];
    const int*   head_ids = (const int*)d_in[5];
    const int*   rel_ids  = (const int*)d_in[6];
    const float* embed    = (const float*)d_in[7];
    const float* W1       = (const float*)d_in[8];
    const float* lw1      = (const float*)d_in[9];
    const float* b1       = (const float*)d_in[10];
    const float* W2       = (const float*)d_in[11];
    const float* lw2      = (const float*)d_in[12];
    const float* b2       = (const float*)d_in[13];
    const float* w_rel    = (const float*)d_in[14];
    const float* eps      = (const float*)d_in[15];
    float* out = (float*)d_out;

    zero_kernel<<<(NN * HD2 / 4 + 255) / 256, 256>>>();
    gather_kernel<<<(NN * HD + 255) / 256, 256>>>(h, embed);
    edge1_kernel<<<EE / 4, 128>>>(src, dst, etypes, norm, W1);
    selfloop1_kernel<<<NN / 16, 128>>>(lw1, b1);
    edge2_kernel<<<EE / 4, 128>>>(src, dst, etypes, norm, W2);
    selfloop2_kernel<<<NN / 8, 256>>>(lw2, b2, eps);
    hr_kernel<<<BQ, 128>>>(head_ids, rel_ids, w_rel);

    static int smem_set = 0;
    int smem_bytes = 2 * BM * LDT * sizeof(unsigned);   // ~135 KB
    if (!smem_set) {
        cudaFuncSetAttribute(decoder_gemm,
                             cudaFuncAttributeMaxDynamicSharedMemorySize, smem_bytes);
        smem_set = 1;
    }
    dim3 grid((NN + BN - 1) / BN, BQ / BM);   // (157, 16)
    decoder_gemm<<<grid, 256, smem_bytes>>>(out);
}